// round 15
// baseline (speedup 1.0000x reference)
#include <cuda_runtime.h>
#include <cuda_fp16.h>

#define NH   16
#define NN   64
#define CC   1024
#define BB   1024

typedef unsigned int u32;
typedef unsigned long long u64;
typedef unsigned short u16;

#define QKVSZ 67108864ull          // 1024*64*1024 elems

// Scratch (allocation-free rule: device globals)
__device__ u16    g_xf16[(size_t)BB * NN * CC];    // x transposed, fp16 [pixel][ch]
__device__ u16    g_wf16[(size_t)4096 * CC];       // Wq,Wk,Wv,Wp fused rows, fp16 RN
__device__ u16    g_qkv16[3ull * QKVSZ];           // q,k,v fp16 [pixel][ch]
__device__ u16    g_of16[(size_t)BB * NN * CC];    // attn out fp16 [pixel][ch]
__device__ u16    g_res16[(size_t)BB * CC * NN];   // residual r fp16 [b][c][n]
__device__ float2 g_partial[BB * 8];               // per-(b, ntile) partial (sum, sumsq)

// ---------------------------------------------------------------------------
// helpers
// ---------------------------------------------------------------------------
__device__ __forceinline__ u32 smem_u32(const void* p) {
    u32 a;
    asm("{ .reg .u64 t; cvta.to.shared.u64 t, %1; cvt.u32.u64 %0, t; }" : "=r"(a) : "l"(p));
    return a;
}
__device__ __forceinline__ void cpa16(u32 dst, const void* src) {
    asm volatile("cp.async.cg.shared.global [%0], [%1], 16;" :: "r"(dst), "l"(src));
}
#define CP_COMMIT() asm volatile("cp.async.commit_group;" ::: "memory")
#define CP_WAIT2()  asm volatile("cp.async.wait_group 2;" ::: "memory")
#define CP_WAIT0()  asm volatile("cp.async.wait_group 0;" ::: "memory")

__device__ __forceinline__ void ldsm_x4(u32* r, u32 addr) {
    asm volatile("ldmatrix.sync.aligned.m8n8.x4.shared.b16 {%0,%1,%2,%3}, [%4];"
        : "=r"(r[0]), "=r"(r[1]), "=r"(r[2]), "=r"(r[3]) : "r"(addr));
}
__device__ __forceinline__ void ldsm_x4t(u32* r, u32 addr) {
    asm volatile("ldmatrix.sync.aligned.m8n8.x4.trans.shared.b16 {%0,%1,%2,%3}, [%4];"
        : "=r"(r[0]), "=r"(r[1]), "=r"(r[2]), "=r"(r[3]) : "r"(addr));
}
__device__ __forceinline__ void mma16816(float* c, const u32* a, const u32* b) {
    asm volatile("mma.sync.aligned.m16n8k16.row.col.f32.f16.f16.f32 "
        "{%0,%1,%2,%3}, {%4,%5,%6,%7}, {%8,%9}, {%0,%1,%2,%3};"
        : "+f"(c[0]), "+f"(c[1]), "+f"(c[2]), "+f"(c[3])
        : "r"(a[0]), "r"(a[1]), "r"(a[2]), "r"(a[3]), "r"(b[0]), "r"(b[1]));
}
// GEMM smem swizzle: rows of 64B (4 chunks), chunk ^= (row>>1)&3
__device__ __forceinline__ u32 sw_addr(u32 base, int row, int kbyte) {
    int chunk = kbyte >> 4, in = kbyte & 15;
    return base + row * 64 + ((chunk ^ ((row >> 1) & 3)) << 4) + in;
}
// attn smem swizzle: rows of 128B (8 chunks), chunk ^= row&7
__device__ __forceinline__ u32 sw128(u32 base, int row, int kbyte) {
    int chunk = kbyte >> 4, in = kbyte & 15;
    return base + row * 128 + ((chunk ^ (row & 7)) << 4) + in;
}
__device__ __forceinline__ u16 f16r(float f) {
    __half h = __float2half_rn(f);
    return *reinterpret_cast<u16*>(&h);
}
__device__ __forceinline__ u32 packh2(float lo, float hi) {
    u32 r;
    asm("cvt.rn.f16x2.f32 %0, %1, %2;" : "=r"(r) : "f"(hi), "f"(lo));
    return r;
}

// GEMM smem: 4 stages x 16KB (A 8K | B 8K per stage)
#define STAGE_BYTES 16384
#define SM_GEMM     (4 * STAGE_BYTES)

// ---------------------------------------------------------------------------
// prep_all: blocks [0,4096) convert 4 weight matrices -> g_wf16;
//           blocks [4096,5120) transpose+convert x -> g_xf16.
// ---------------------------------------------------------------------------
__global__ void __launch_bounds__(256) prep_all_kernel(
    const float* __restrict__ Wq, const float* __restrict__ Wk,
    const float* __restrict__ Wv, const float* __restrict__ Wp,
    const float* __restrict__ x)
{
    __shared__ u16 hT[64][72];
    int blk = blockIdx.x;
    const int t = threadIdx.x;
    if (blk < 4096) {
        int mat = blk >> 10;
        const float* src = (mat == 0) ? Wq : (mat == 1) ? Wk : (mat == 2) ? Wv : Wp;
        size_t idx = ((size_t)(blk & 1023) * 256 + t) * 4;
        float4 v = *(const float4*)(src + idx);
        size_t o = (size_t)mat * 1048576 + idx;
        ushort4 h;
        h.x = f16r(v.x); h.y = f16r(v.y); h.z = f16r(v.z); h.w = f16r(v.w);
        *(ushort4*)(g_wf16 + o) = h;
        return;
    }
    const int b = blk - 4096;
    const float* xb = x + (size_t)b * 65536;
    for (int ct = 0; ct < 16; ++ct) {
        #pragma unroll
        for (int i = 0; i < 16; ++i) {
            int idx = i * 256 + t, c = idx >> 6, n = idx & 63;
            hT[n][c] = f16r(xb[(ct * 64 + c) * 64 + n]);
        }
        __syncthreads();
        #pragma unroll
        for (int i = 0; i < 2; ++i) {
            int idx = i * 256 + t;
            int n = idx >> 3, c8 = (idx & 7) << 3;
            size_t o = (size_t)(b * 64 + n) * 1024 + ct * 64 + c8;
            *(uint4*)(g_xf16 + o) = *(const uint4*)&hT[n][c8];
        }
        __syncthreads();
    }
}

// ---------------------------------------------------------------------------
// GEMM core: C[128 pix][128 ch] = A x B^T over K=1024, fp16 single-pass.
// ---------------------------------------------------------------------------
__device__ __forceinline__ void gemm_issue_stage(
    u32 sb, int s, int c, const char* gA, const char* gB)
{
    const int t = threadIdx.x;
    const char* gsrc[2] = {gA, gB};
    u32 stb = sb + s * STAGE_BYTES;
    #pragma unroll
    for (int arr = 0; arr < 2; ++arr) {
        #pragma unroll
        for (int r2 = 0; r2 < 2; ++r2) {
            int ch = t + r2 * 256;
            int row = ch >> 2, part = ch & 3;
            u32 dst = stb + arr * 8192 + row * 64 + ((part ^ ((row >> 1) & 3)) << 4);
            const char* src = gsrc[arr] + (size_t)row * 2048 + c * 64 + part * 16;
            cpa16(dst, src);
        }
    }
    CP_COMMIT();
}

__device__ __forceinline__ void gemm_compute_stage(u32 sb, int s, float acc[4][4][4],
                                                   int wm, int wn, int lane)
{
    u32 stb = sb + s * STAGE_BYTES;
    u32 pA = stb, pB = stb + 8192;
    const int arow = lane & 15;
    const int akb  = (lane >> 4) << 4;
    const int brow = (lane & 7) + ((lane & 16) >> 1);
    const int bkb  = (lane & 8) << 1;
    #pragma unroll
    for (int ks = 0; ks < 2; ++ks) {
        int kb = ks * 32;
        u32 A[4][4], B[4][2];
        #pragma unroll
        for (int i = 0; i < 4; ++i)
            ldsm_x4(A[i], sw_addr(pA, wm + i * 16 + arow, kb + akb));
        #pragma unroll
        for (int jp = 0; jp < 2; ++jp) {
            u32 r[4];
            ldsm_x4(r, sw_addr(pB, wn + jp * 16 + brow, kb + bkb));
            B[jp*2][0] = r[0]; B[jp*2][1] = r[1];
            B[jp*2+1][0] = r[2]; B[jp*2+1][1] = r[3];
        }
        #pragma unroll
        for (int i = 0; i < 4; ++i)
            #pragma unroll
            for (int j = 0; j < 4; ++j) mma16816(acc[i][j], A[i], B[j]);
    }
}

#define GEMM_MAINLOOP(gA, gB, acc)                                              \
    do {                                                                        \
        gemm_issue_stage(sb, 0, 0, gA, gB);                                     \
        gemm_issue_stage(sb, 1, 1, gA, gB);                                     \
        gemm_issue_stage(sb, 2, 2, gA, gB);                                     \
        for (int c = 0; c < 32; ++c) {                                          \
            CP_WAIT2();                                                         \
            __syncthreads();                                                    \
            gemm_compute_stage(sb, c & 3, acc, wm, wn, lane);                   \
            if (c + 3 < 32) gemm_issue_stage(sb, (c + 3) & 3, c + 3, gA, gB);   \
            else CP_COMMIT();                                                   \
        }                                                                       \
    } while (0)

// ---------------------------------------------------------------------------
// QKV GEMM: grid (24 ntiles, 512 pixel-groups). out fp16 q/k/v [pixel][ch]+bias
// Epilogue bounces C through smem for fully-coalesced uint4 stores.
// ---------------------------------------------------------------------------
__global__ void __launch_bounds__(256, 2) qkv_gemm_kernel(
    const float* __restrict__ bq, const float* __restrict__ bk,
    const float* __restrict__ bv)
{
    extern __shared__ char smc[];
    const u32 sb = smem_u32(smc);
    const int t = threadIdx.x, wid = t >> 5, lane = t & 31;
    const int grp = lane >> 2, tig = lane & 3;
    const int wm = (wid & 1) << 6, wn = (wid >> 1) << 5;
    const int nt = blockIdx.x, mg = blockIdx.y;

    const char* gA = (const char*)g_xf16 + (size_t)mg * 128 * 2048;
    const char* gB = (const char*)g_wf16 + (size_t)nt * 128 * 2048;

    float acc[4][4][4];
    #pragma unroll
    for (int i = 0; i < 4; ++i)
        #pragma unroll
        for (int j = 0; j < 4; ++j) { acc[i][j][0]=0.f; acc[i][j][1]=0.f; acc[i][j][2]=0.f; acc[i][j][3]=0.f; }

    GEMM_MAINLOOP(gA, gB, acc);

    const int sel = nt >> 3;
    const int cbase = (nt & 7) * 128;
    const float* bias = (sel == 0) ? bq : (sel == 1) ? bk : bv;
    u16* out = g_qkv16 + (size_t)sel * QKVSZ;

    __syncthreads();   // all warps done with stage smem before reuse
    // bounce: fp16-packed C tile [128 rows][64 u32], pad-65 rows (33.3KB)
    u32* ot = (u32*)smc;
    #pragma unroll
    for (int i = 0; i < 4; ++i) {
        int pm = wm + i * 16 + grp;
        #pragma unroll
        for (int j = 0; j < 4; ++j) {
            int col = cbase + wn + j * 8 + tig * 2;
            float b0 = bias[col], b1 = bias[col + 1];
            int cu = (wn >> 1) + j * 4 + tig;
            ot[pm * 65 + cu]       = packh2(acc[i][j][0] + b0, acc[i][j][1] + b1);
            ot[(pm + 8) * 65 + cu] = packh2(acc[i][j][2] + b0, acc[i][j][3] + b1);
        }
    }
    __syncthreads();
    // coalesced write: each row = 128 fp16 = 16 uint4
    #pragma unroll
    for (int it = 0; it < 8; ++it) {
        int idx = it * 256 + t;             // 0..2047
        int row = idx >> 4, seg = idx & 15;
        const u32* rp = ot + row * 65 + seg * 4;
        uint4 w4 = make_uint4(rp[0], rp[1], rp[2], rp[3]);
        *(uint4*)(out + (size_t)(mg * 128 + row) * 1024 + cbase + seg * 8) = w4;
    }
}

// ---------------------------------------------------------------------------
// Proj GEMM: grid (8 ntiles, 512 pixel-groups). A = attn out fp16.
// Epilogue: smem transpose -> residual r = g*(out+bias) + (1-g)*x -> fp16
// [b][c][n], plus deterministic per-(batch, ntile) LN partials (fp32, pre-round).
// ---------------------------------------------------------------------------
__global__ void __launch_bounds__(256, 2) proj_gemm_kernel(
    const float* __restrict__ bp, const float* __restrict__ x,
    const float* __restrict__ gamma_p)
{
    extern __shared__ char smc[];
    __shared__ float red1[8], red2[8];
    const u32 sb = smem_u32(smc);
    const int t = threadIdx.x, wid = t >> 5, lane = t & 31;
    const int grp = lane >> 2, tig = lane & 3;
    const int wm = (wid & 1) << 6, wn = (wid >> 1) << 5;
    const int nt = blockIdx.x, mg = blockIdx.y;

    const char* gA = (const char*)g_of16 + (size_t)mg * 128 * 2048;
    const char* gB = (const char*)g_wf16 + (size_t)(3072 + nt * 128) * 2048;

    float acc[4][4][4];
    #pragma unroll
    for (int i = 0; i < 4; ++i)
        #pragma unroll
        for (int j = 0; j < 4; ++j) { acc[i][j][0]=0.f; acc[i][j][1]=0.f; acc[i][j][2]=0.f; acc[i][j][3]=0.f; }

    GEMM_MAINLOOP(gA, gB, acc);

    const float g = gamma_p[0], og = 1.0f - g;
    __syncthreads();
    float* tile = (float*)smc;
    #pragma unroll
    for (int half = 0; half < 2; ++half) {
        if ((wm >> 6) == half) {
            #pragma unroll
            for (int i = 0; i < 4; ++i) {
                int pm = i * 16 + grp;
                #pragma unroll
                for (int j = 0; j < 4; ++j) {
                    int cc = wn + j * 8 + tig * 2;
                    *(float2*)&tile[pm * 130 + cc] = make_float2(acc[i][j][0], acc[i][j][1]);
                    *(float2*)&tile[(pm + 8) * 130 + cc] = make_float2(acc[i][j][2], acc[i][j][3]);
                }
            }
        }
        __syncthreads();
        int b = mg * 2 + half;
        float s1 = 0.f, s2 = 0.f;
        #pragma unroll
        for (int it = 0; it < 8; ++it) {
            int idx = it * 256 + t;
            int cc = idx >> 4, n4 = (idx & 15) << 2;
            int ch = nt * 128 + cc;
            float bi = bp[ch];
            size_t off = (size_t)b * 65536 + (size_t)ch * 64 + n4;
            float4 xv = *(const float4*)(x + off);
            float4 v;
            v.x = g * (tile[(n4 + 0) * 130 + cc] + bi) + og * xv.x;
            v.y = g * (tile[(n4 + 1) * 130 + cc] + bi) + og * xv.y;
            v.z = g * (tile[(n4 + 2) * 130 + cc] + bi) + og * xv.z;
            v.w = g * (tile[(n4 + 3) * 130 + cc] + bi) + og * xv.w;
            ushort4 hv;
            hv.x = f16r(v.x); hv.y = f16r(v.y); hv.z = f16r(v.z); hv.w = f16r(v.w);
            *(ushort4*)(g_res16 + off) = hv;
            s1 += v.x + v.y + v.z + v.w;
            s2 += v.x * v.x + v.y * v.y + v.z * v.z + v.w * v.w;
        }
        // deterministic CTA reduction of partial stats
        #pragma unroll
        for (int o = 16; o; o >>= 1) {
            s1 += __shfl_xor_sync(0xffffffffu, s1, o);
            s2 += __shfl_xor_sync(0xffffffffu, s2, o);
        }
        if (lane == 0) { red1[wid] = s1; red2[wid] = s2; }
        __syncthreads();
        if (t == 0) {
            float a1 = 0.f, a2 = 0.f;
            #pragma unroll
            for (int w = 0; w < 8; ++w) { a1 += red1[w]; a2 += red2[w]; }
            g_partial[b * 8 + nt] = make_float2(a1, a2);
        }
        __syncthreads();
    }
}

// ---------------------------------------------------------------------------
// Attention (tensor-core): one CTA per (b,h), 128 threads / 4 warps.
// ---------------------------------------------------------------------------
__global__ void __launch_bounds__(128) attn_kernel(const float* __restrict__ temp_p)
{
    __shared__ __align__(128) u16 qs[4096];   // [n][d] fp16, sw128
    __shared__ __align__(128) u16 kk[4096];   // [m][d]
    __shared__ __align__(128) u16 vv[4096];   // [m][d]
    __shared__ float scq[64], sck[64];

    const int t = threadIdx.x, lane = t & 31, wid = t >> 5;
    const int b = blockIdx.x >> 4, h = blockIdx.x & 15;
    const u32 q0 = smem_u32(qs), k0 = smem_u32(kk), v0 = smem_u32(vv);

    // ---- load q/k/v tiles (64 x 64 fp16 each) via cp.async ----
    {
        u32 bases[3] = {q0, k0, v0};
        #pragma unroll
        for (int i = 0; i < 12; ++i) {
            int idx = t + i * 128;           // 0..1535
            int arr = idx >> 9, rem = idx & 511;
            int row = rem >> 3, ch = rem & 7;
            u32 dst = bases[arr] + row * 128 + ((ch ^ (row & 7)) << 4);
            const char* src = (const char*)(g_qkv16 + (size_t)arr * QKVSZ)
                            + ((size_t)(b * 64 + row) * 1024 + h * 64) * 2 + ch * 16;
            cpa16(dst, src);
        }
        CP_COMMIT();
        CP_WAIT0();
        __syncthreads();
    }

    // ---- per-d column sums of squares (vectorized: u32 loads, d-pairs) ----
    {
        float tinv = 1.0f / (temp_p[0] + 1e-6f);
        const u16* barr = (wid < 2) ? qs : kk;
        const int dp = ((wid & 1) << 4) + (lane & 15);   // 0..31
        const int half = lane >> 4;                       // 0: rows 0-31, 1: 32-63
        const int cb = dp >> 2;
        const int io = (dp * 4) & 15;
        float sx = 0.f, sy = 0.f;
        #pragma unroll 8
        for (int i = 0; i < 32; ++i) {
            int row = half * 32 + i;
            u32 off = (u32)(row * 128 + ((cb ^ (row & 7)) << 4) + io) >> 1;
            u32 v = *(const u32*)(barr + off);
            float2 f = __half22float2(*(__half2*)&v);
            sx += f.x * f.x;
            sy += f.y * f.y;
        }
        sx += __shfl_xor_sync(0xffffffffu, sx, 16);
        sy += __shfl_xor_sync(0xffffffffu, sy, 16);
        if (lane < 16) {
            float2 inv;
            inv.x = 1.0f / fmaxf(sqrtf(sx), 1e-12f);
            inv.y = 1.0f / fmaxf(sqrtf(sy), 1e-12f);
            if (wid < 2) *(float2*)&scq[dp * 2] = inv;
            else         *(float2*)&sck[dp * 2] = inv;
        }
        __syncthreads();
        if (t < 64) scq[t] = scq[t] * sck[t] * tinv;
        __syncthreads();
    }

    // ---- fold combined scale into q (fp16, in place) ----
    {
        u32* qw = (u32*)qs;
        #pragma unroll
        for (int i = 0; i < 16; ++i) {
            int idx = t + i * 128;
            int row = idx >> 5, pos = idx & 31;
            int ui = (row * 128 + (((pos >> 2) ^ (row & 7)) << 4) + (pos & 3) * 4) >> 2;
            float2 f = __half22float2(*(__half2*)&qw[ui]);
            f.x *= scq[pos * 2];
            f.y *= scq[pos * 2 + 1];
            qw[ui] = packh2(f.x, f.y);
        }
        __syncthreads();
    }

    // ---- S = qhat^T khat ----
    const int wm = wid << 4;
    float sa[8][4];
    #pragma unroll
    for (int j = 0; j < 8; ++j) { sa[j][0]=0.f; sa[j][1]=0.f; sa[j][2]=0.f; sa[j][3]=0.f; }
    {
        const int arow = lane & 15, akb = (lane >> 4) << 4;
        const int br = (lane & 7) + ((lane & 16) >> 1), bkb = (lane & 8) << 1;
        #pragma unroll
        for (int ks = 0; ks < 4; ++ks) {
            int kb = ks * 32;
            u32 A[4];
            ldsm_x4(A, sw128(q0, wm + arow, kb + akb));
            #pragma unroll
            for (int jp = 0; jp < 4; ++jp) {
                u32 r[4];
                ldsm_x4(r, sw128(k0, jp * 16 + br, kb + bkb));
                mma16816(sa[jp * 2], A, r);
                mma16816(sa[jp * 2 + 1], A, r + 2);
            }
        }
    }

    // ---- softmax + repack P into A-fragments ----
    u32 pa[4][4];
    {
        float mx0 = -1e30f, mx1 = -1e30f;
        #pragma unroll
        for (int j = 0; j < 8; ++j) {
            mx0 = fmaxf(mx0, fmaxf(sa[j][0], sa[j][1]));
            mx1 = fmaxf(mx1, fmaxf(sa[j][2], sa[j][3]));
        }
        #pragma unroll
        for (int o = 1; o <= 2; o <<= 1) {
            mx0 = fmaxf(mx0, __shfl_xor_sync(0xffffffffu, mx0, o));
            mx1 = fmaxf(mx1, __shfl_xor_sync(0xffffffffu, mx1, o));
        }
        float sum0 = 0.f, sum1 = 0.f;
        #pragma unroll
        for (int j = 0; j < 8; ++j) {
            sa[j][0] = __expf(sa[j][0] - mx0); sum0 += sa[j][0];
            sa[j][1] = __expf(sa[j][1] - mx0); sum0 += sa[j][1];
            sa[j][2] = __expf(sa[j][2] - mx1); sum1 += sa[j][2];
            sa[j][3] = __expf(sa[j][3] - mx1); sum1 += sa[j][3];
        }
        #pragma unroll
        for (int o = 1; o <= 2; o <<= 1) {
            sum0 += __shfl_xor_sync(0xffffffffu, sum0, o);
            sum1 += __shfl_xor_sync(0xffffffffu, sum1, o);
        }
        float r0 = 1.0f / sum0, r1 = 1.0f / sum1;
        #pragma unroll
        for (int ks = 0; ks < 4; ++ks) {
            pa[ks][0] = packh2(sa[2*ks][0] * r0, sa[2*ks][1] * r0);
            pa[ks][1] = packh2(sa[2*ks][2] * r1, sa[2*ks][3] * r1);
            pa[ks][2] = packh2(sa[2*ks+1][0] * r0, sa[2*ks+1][1] * r0);
            pa[ks][3] = packh2(sa[2*ks+1][2] * r1, sa[2*ks+1][3] * r1);
        }
    }

    // ---- O = P V ----
    float oa[8][4];
    #pragma unroll
    for (int j = 0; j < 8; ++j) { oa[j][0]=0.f; oa[j][1]=0.f; oa[j][2]=0.f; oa[j][3]=0.f; }
    {
        const int vrow = lane & 15, vdb = (lane >> 4) << 4;
        #pragma unroll
        for (int ks = 0; ks < 4; ++ks) {
            #pragma unroll
            for (int Dp = 0; Dp < 4; ++Dp) {
                u32 r[4];
                ldsm_x4t(r, sw128(v0, ks * 16 + vrow, Dp * 32 + vdb));
                mma16816(oa[Dp * 2], pa[ks], r);
                mma16816(oa[Dp * 2 + 1], pa[ks], r + 2);
            }
        }
    }
    __syncthreads();

    // ---- bounce O through smem, coalesced fp16 writes ----
    {
        u32* bn = (u32*)qs;
        int grp = lane >> 2, tg = lane & 3;
        #pragma unroll
        for (int jd = 0; jd < 8; ++jd) {
            int c = jd * 4 + tg;
            bn[(wm + grp) * 33 + c]     = packh2(oa[jd][0], oa[jd][1]);
            bn[(wm + grp + 8) * 33 + c] = packh2(oa[jd][2], oa[jd][3]);
        }
        __syncthreads();
        u16* outg = g_of16 + (size_t)(b * 64) * 1024 + h * 64;
        #pragma unroll
        for (int i = 0; i < 16; ++i) {
            int idx = t + i * 128;
            int row = idx >> 5, c = idx & 31;
            *(u32*)(outg + (size_t)row * 1024 + c * 2) = bn[row * 33 + c];
        }
    }
}

// ---------------------------------------------------------------------------
// LN apply: one CTA per batch, 512 threads. Stats from g_partial (8 per batch),
// single pass over fp16 residual.  y = (r - mu) * rstd * ln_w + ln_b
// ---------------------------------------------------------------------------
__global__ void __launch_bounds__(512) ln_kernel(
    const float* __restrict__ lnw, const float* __restrict__ lnb,
    float* __restrict__ y)
{
    __shared__ float sh[2];
    const int b = blockIdx.x, t = threadIdx.x;
    if (t == 0) {
        float s1 = 0.f, s2 = 0.f;
        #pragma unroll
        for (int w = 0; w < 8; ++w) {
            float2 p = g_partial[b * 8 + w];
            s1 += p.x; s2 += p.y;
        }
        float mu  = s1 * (1.0f / 65536.0f);
        float var = s2 * (1.0f / 65536.0f) - mu * mu;
        sh[0] = mu;
        sh[1] = rsqrtf(var + 1e-5f);
    }
    __syncthreads();
    const float mu = sh[0], rs = sh[1];
    const u16* rb = g_res16 + (size_t)b * 65536;
    float* yb = y + (size_t)b * 65536;
    #pragma unroll 2
    for (int i = t * 8; i < 65536; i += 4096) {
        uint4 pr = *(const uint4*)(rb + i);      // 8 fp16 residuals
        float2 p0 = __half22float2(*(__half2*)&pr.x);
        float2 p1 = __half22float2(*(__half2*)&pr.y);
        float2 p2 = __half22float2(*(__half2*)&pr.z);
        float2 p3 = __half22float2(*(__half2*)&pr.w);
        float4 w0 = *(const float4*)(lnw + i);
        float4 w1 = *(const float4*)(lnw + i + 4);
        float4 b0 = *(const float4*)(lnb + i);
        float4 b1 = *(const float4*)(lnb + i + 4);
        float4 o0, o1;
        o0.x = (p0.x - mu) * rs * w0.x + b0.x;
        o0.y = (p0.y - mu) * rs * w0.y + b0.y;
        o0.z = (p1.x - mu) * rs * w0.z + b0.z;
        o0.w = (p1.y - mu) * rs * w0.w + b0.w;
        o1.x = (p2.x - mu) * rs * w1.x + b1.x;
        o1.y = (p2.y - mu) * rs * w1.y + b1.y;
        o1.z = (p3.x - mu) * rs * w1.z + b1.z;
        o1.w = (p3.y - mu) * rs * w1.w + b1.w;
        *(float4*)(yb + i) = o0;
        *(float4*)(yb + i + 4) = o1;
    }
}

// ---------------------------------------------------------------------------
extern "C" void kernel_launch(void* const* d_in, const int* in_sizes, int n_in,
                              void* d_out, int out_size)
{
    const float* x     = (const float*)d_in[0];
    const float* Wq    = (const float*)d_in[1];
    const float* bq    = (const float*)d_in[2];
    const float* Wk    = (const float*)d_in[3];
    const float* bk    = (const float*)d_in[4];
    const float* Wv    = (const float*)d_in[5];
    const float* bv    = (const float*)d_in[6];
    const float* Wp    = (const float*)d_in[7];
    const float* bp    = (const float*)d_in[8];
    const float* gamma = (const float*)d_in[9];
    const float* temp  = (const float*)d_in[10];
    const float* lnw   = (const float*)d_in[11];
    const float* lnb   = (const float*)d_in[12];
    float* y = (float*)d_out;

    cudaFuncSetAttribute(qkv_gemm_kernel, cudaFuncAttributeMaxDynamicSharedMemorySize, SM_GEMM);
    cudaFuncSetAttribute(proj_gemm_kernel, cudaFuncAttributeMaxDynamicSharedMemorySize, SM_GEMM);

    prep_all_kernel<<<4096 + BB, 256>>>(Wq, Wk, Wv, Wp, x);
    qkv_gemm_kernel<<<dim3(24, 512), 256, SM_GEMM>>>(bq, bk, bv);
    attn_kernel<<<BB * NH, 128>>>(temp);
    proj_gemm_kernel<<<dim3(8, 512), 256, SM_GEMM>>>(bp, x, gamma);
    ln_kernel<<<BB, 512>>>(lnw, lnb, y);
}

// round 17
// speedup vs baseline: 1.0570x; 1.0570x over previous
#include <cuda_runtime.h>
#include <cuda_fp16.h>

#define NH   16
#define NN   64
#define CC   1024
#define BB   1024

typedef unsigned int u32;
typedef unsigned long long u64;
typedef unsigned short u16;

#define QKVSZ 67108864ull          // 1024*64*1024 elems

// Scratch (allocation-free rule: device globals)
__device__ u16    g_xf16[(size_t)BB * NN * CC];    // x transposed, fp16 [pixel][ch]
__device__ u16    g_wf16[(size_t)4096 * CC];       // Wq,Wk,Wv,Wp fused rows, fp16 RN
__device__ u16    g_qkv16[3ull * QKVSZ];           // q,k,v fp16 [pixel][ch]
__device__ u16    g_of16[(size_t)BB * NN * CC];    // attn out fp16 [pixel][ch]
__device__ u16    g_res16[(size_t)BB * CC * NN];   // residual r fp16 [b][c][n]
__device__ float2 g_partial[BB * 8];               // per-(b, ntile) partial (sum, sumsq)

// ---------------------------------------------------------------------------
// helpers
// ---------------------------------------------------------------------------
__device__ __forceinline__ u32 smem_u32(const void* p) {
    u32 a;
    asm("{ .reg .u64 t; cvta.to.shared.u64 t, %1; cvt.u32.u64 %0, t; }" : "=r"(a) : "l"(p));
    return a;
}
__device__ __forceinline__ void cpa16(u32 dst, const void* src) {
    asm volatile("cp.async.cg.shared.global [%0], [%1], 16;" :: "r"(dst), "l"(src));
}
#define CP_COMMIT() asm volatile("cp.async.commit_group;" ::: "memory")
#define CP_WAIT1()  asm volatile("cp.async.wait_group 1;" ::: "memory")
#define CP_WAIT0()  asm volatile("cp.async.wait_group 0;" ::: "memory")

__device__ __forceinline__ void ldsm_x4(u32* r, u32 addr) {
    asm volatile("ldmatrix.sync.aligned.m8n8.x4.shared.b16 {%0,%1,%2,%3}, [%4];"
        : "=r"(r[0]), "=r"(r[1]), "=r"(r[2]), "=r"(r[3]) : "r"(addr));
}
__device__ __forceinline__ void ldsm_x4t(u32* r, u32 addr) {
    asm volatile("ldmatrix.sync.aligned.m8n8.x4.trans.shared.b16 {%0,%1,%2,%3}, [%4];"
        : "=r"(r[0]), "=r"(r[1]), "=r"(r[2]), "=r"(r[3]) : "r"(addr));
}
__device__ __forceinline__ void mma16816(float* c, const u32* a, const u32* b) {
    asm volatile("mma.sync.aligned.m16n8k16.row.col.f32.f16.f16.f32 "
        "{%0,%1,%2,%3}, {%4,%5,%6,%7}, {%8,%9}, {%0,%1,%2,%3};"
        : "+f"(c[0]), "+f"(c[1]), "+f"(c[2]), "+f"(c[3])
        : "r"(a[0]), "r"(a[1]), "r"(a[2]), "r"(a[3]), "r"(b[0]), "r"(b[1]));
}
// 128B-row swizzle: rows of 128B (8 chunks), chunk ^= row&7 (GEMM stages + attn)
__device__ __forceinline__ u32 sw128(u32 base, int row, int kbyte) {
    int chunk = kbyte >> 4, in = kbyte & 15;
    return base + row * 128 + ((chunk ^ (row & 7)) << 4) + in;
}
__device__ __forceinline__ u16 f16r(float f) {
    __half h = __float2half_rn(f);
    return *reinterpret_cast<u16*>(&h);
}
__device__ __forceinline__ u32 packh2(float lo, float hi) {
    u32 r;
    asm("cvt.rn.f16x2.f32 %0, %1, %2;" : "=r"(r) : "f"(hi), "f"(lo));
    return r;
}

// GEMM smem: 3 stages x 32KB (A 16K | B 16K per stage), BK=64
#define STAGE_BYTES 32768
#define SM_GEMM     (3 * STAGE_BYTES)

// ---------------------------------------------------------------------------
// prep_all: blocks [0,4096) convert 4 weight matrices -> g_wf16;
//           blocks [4096,5120) transpose+convert x -> g_xf16.
// ---------------------------------------------------------------------------
__global__ void __launch_bounds__(256) prep_all_kernel(
    const float* __restrict__ Wq, const float* __restrict__ Wk,
    const float* __restrict__ Wv, const float* __restrict__ Wp,
    const float* __restrict__ x)
{
    __shared__ u16 hT[64][72];
    int blk = blockIdx.x;
    const int t = threadIdx.x;
    if (blk < 4096) {
        int mat = blk >> 10;
        const float* src = (mat == 0) ? Wq : (mat == 1) ? Wk : (mat == 2) ? Wv : Wp;
        size_t idx = ((size_t)(blk & 1023) * 256 + t) * 4;
        float4 v = *(const float4*)(src + idx);
        size_t o = (size_t)mat * 1048576 + idx;
        ushort4 h;
        h.x = f16r(v.x); h.y = f16r(v.y); h.z = f16r(v.z); h.w = f16r(v.w);
        *(ushort4*)(g_wf16 + o) = h;
        return;
    }
    const int b = blk - 4096;
    const float* xb = x + (size_t)b * 65536;
    for (int ct = 0; ct < 16; ++ct) {
        #pragma unroll
        for (int i = 0; i < 16; ++i) {
            int idx = i * 256 + t, c = idx >> 6, n = idx & 63;
            hT[n][c] = f16r(xb[(ct * 64 + c) * 64 + n]);
        }
        __syncthreads();
        #pragma unroll
        for (int i = 0; i < 2; ++i) {
            int idx = i * 256 + t;
            int n = idx >> 3, c8 = (idx & 7) << 3;
            size_t o = (size_t)(b * 64 + n) * 1024 + ct * 64 + c8;
            *(uint4*)(g_xf16 + o) = *(const uint4*)&hT[n][c8];
        }
        __syncthreads();
    }
}

// ---------------------------------------------------------------------------
// GEMM core: C[128 pix][128 ch] = A x B^T over K=1024, fp16, BK=64 stages.
// Stage: A 128 rows x 128B + B 128 rows x 128B, sw128 swizzle.
// ---------------------------------------------------------------------------
__device__ __forceinline__ void gemm_issue_stage(
    u32 sb, int s, int c, const char* gA, const char* gB)
{
    const int t = threadIdx.x;
    const char* gsrc[2] = {gA, gB};
    u32 stb = sb + s * STAGE_BYTES;
    #pragma unroll
    for (int arr = 0; arr < 2; ++arr) {
        #pragma unroll
        for (int r4 = 0; r4 < 4; ++r4) {
            int ch = t + r4 * 256;              // 0..1023
            int row = ch >> 3, part = ch & 7;
            u32 dst = stb + arr * 16384 + row * 128 + ((part ^ (row & 7)) << 4);
            const char* src = gsrc[arr] + (size_t)row * 2048 + c * 128 + part * 16;
            cpa16(dst, src);
        }
    }
    CP_COMMIT();
}

__device__ __forceinline__ void gemm_compute_stage(u32 sb, int s, float acc[4][4][4],
                                                   int wm, int wn, int lane)
{
    u32 stb = sb + s * STAGE_BYTES;
    u32 pA = stb, pB = stb + 16384;
    const int arow = lane & 15;
    const int akb  = (lane >> 4) << 4;
    const int brow = (lane & 7) + ((lane & 16) >> 1);
    const int bkb  = (lane & 8) << 1;
    #pragma unroll
    for (int ks = 0; ks < 4; ++ks) {
        int kb = ks * 32;
        u32 A[4][4], B[4][2];
        #pragma unroll
        for (int i = 0; i < 4; ++i)
            ldsm_x4(A[i], sw128(pA, wm + i * 16 + arow, kb + akb));
        #pragma unroll
        for (int jp = 0; jp < 2; ++jp) {
            u32 r[4];
            ldsm_x4(r, sw128(pB, wn + jp * 16 + brow, kb + bkb));
            B[jp*2][0] = r[0]; B[jp*2][1] = r[1];
            B[jp*2+1][0] = r[2]; B[jp*2+1][1] = r[3];
        }
        #pragma unroll
        for (int i = 0; i < 4; ++i)
            #pragma unroll
            for (int j = 0; j < 4; ++j) mma16816(acc[i][j], A[i], B[j]);
    }
}

#define GEMM_MAINLOOP(gA, gB, acc)                                              \
    do {                                                                        \
        gemm_issue_stage(sb, 0, 0, gA, gB);                                     \
        gemm_issue_stage(sb, 1, 1, gA, gB);                                     \
        for (int c = 0; c < 16; ++c) {                                          \
            CP_WAIT1();                                                         \
            __syncthreads();                                                    \
            gemm_compute_stage(sb, c % 3, acc, wm, wn, lane);                   \
            if (c + 2 < 16) gemm_issue_stage(sb, (c + 2) % 3, c + 2, gA, gB);   \
            else CP_COMMIT();                                                   \
        }                                                                       \
    } while (0)

// ---------------------------------------------------------------------------
// QKV GEMM: grid (24 ntiles, 512 pixel-groups). out fp16 q/k/v [pixel][ch]+bias
// Epilogue bounces C through smem for fully-coalesced uint4 stores.
// ---------------------------------------------------------------------------
__global__ void __launch_bounds__(256, 2) qkv_gemm_kernel(
    const float* __restrict__ bq, const float* __restrict__ bk,
    const float* __restrict__ bv)
{
    extern __shared__ char smc[];
    const u32 sb = smem_u32(smc);
    const int t = threadIdx.x, wid = t >> 5, lane = t & 31;
    const int grp = lane >> 2, tig = lane & 3;
    const int wm = (wid & 1) << 6, wn = (wid >> 1) << 5;
    const int nt = blockIdx.x, mg = blockIdx.y;

    const char* gA = (const char*)g_xf16 + (size_t)mg * 128 * 2048;
    const char* gB = (const char*)g_wf16 + (size_t)nt * 128 * 2048;

    float acc[4][4][4];
    #pragma unroll
    for (int i = 0; i < 4; ++i)
        #pragma unroll
        for (int j = 0; j < 4; ++j) { acc[i][j][0]=0.f; acc[i][j][1]=0.f; acc[i][j][2]=0.f; acc[i][j][3]=0.f; }

    GEMM_MAINLOOP(gA, gB, acc);

    const int sel = nt >> 3;
    const int cbase = (nt & 7) * 128;
    const float* bias = (sel == 0) ? bq : (sel == 1) ? bk : bv;
    u16* out = g_qkv16 + (size_t)sel * QKVSZ;

    __syncthreads();   // all warps done with stage smem before reuse
    // bounce: fp16-packed C tile [128 rows][64 u32], pad-65 rows (33.3KB)
    u32* ot = (u32*)smc;
    #pragma unroll
    for (int i = 0; i < 4; ++i) {
        int pm = wm + i * 16 + grp;
        #pragma unroll
        for (int j = 0; j < 4; ++j) {
            int col = cbase + wn + j * 8 + tig * 2;
            float b0 = bias[col], b1 = bias[col + 1];
            int cu = (wn >> 1) + j * 4 + tig;
            ot[pm * 65 + cu]       = packh2(acc[i][j][0] + b0, acc[i][j][1] + b1);
            ot[(pm + 8) * 65 + cu] = packh2(acc[i][j][2] + b0, acc[i][j][3] + b1);
        }
    }
    __syncthreads();
    // coalesced write: each row = 128 fp16 = 16 uint4
    #pragma unroll
    for (int it = 0; it < 8; ++it) {
        int idx = it * 256 + t;             // 0..2047
        int row = idx >> 4, seg = idx & 15;
        const u32* rp = ot + row * 65 + seg * 4;
        uint4 w4 = make_uint4(rp[0], rp[1], rp[2], rp[3]);
        *(uint4*)(out + (size_t)(mg * 128 + row) * 1024 + cbase + seg * 8) = w4;
    }
}

// ---------------------------------------------------------------------------
// Proj GEMM: grid (8 ntiles, 512 pixel-groups). A = attn out fp16.
// Epilogue: smem transpose -> residual r = g*(out+bias) + (1-g)*x -> fp16
// [b][c][n], plus deterministic per-(batch, ntile) LN partials (fp32, pre-round).
// ---------------------------------------------------------------------------
__global__ void __launch_bounds__(256, 2) proj_gemm_kernel(
    const float* __restrict__ bp, const float* __restrict__ x,
    const float* __restrict__ gamma_p)
{
    extern __shared__ char smc[];
    __shared__ float red1[8], red2[8];
    const u32 sb = smem_u32(smc);
    const int t = threadIdx.x, wid = t >> 5, lane = t & 31;
    const int grp = lane >> 2, tig = lane & 3;
    const int wm = (wid & 1) << 6, wn = (wid >> 1) << 5;
    const int nt = blockIdx.x, mg = blockIdx.y;

    const char* gA = (const char*)g_of16 + (size_t)mg * 128 * 2048;
    const char* gB = (const char*)g_wf16 + (size_t)(3072 + nt * 128) * 2048;

    float acc[4][4][4];
    #pragma unroll
    for (int i = 0; i < 4; ++i)
        #pragma unroll
        for (int j = 0; j < 4; ++j) { acc[i][j][0]=0.f; acc[i][j][1]=0.f; acc[i][j][2]=0.f; acc[i][j][3]=0.f; }

    GEMM_MAINLOOP(gA, gB, acc);

    const float g = gamma_p[0], og = 1.0f - g;
    __syncthreads();
    float* tile = (float*)smc;
    #pragma unroll
    for (int half = 0; half < 2; ++half) {
        if ((wm >> 6) == half) {
            #pragma unroll
            for (int i = 0; i < 4; ++i) {
                int pm = i * 16 + grp;
                #pragma unroll
                for (int j = 0; j < 4; ++j) {
                    int cc = wn + j * 8 + tig * 2;
                    *(float2*)&tile[pm * 130 + cc] = make_float2(acc[i][j][0], acc[i][j][1]);
                    *(float2*)&tile[(pm + 8) * 130 + cc] = make_float2(acc[i][j][2], acc[i][j][3]);
                }
            }
        }
        __syncthreads();
        int b = mg * 2 + half;
        float s1 = 0.f, s2 = 0.f;
        #pragma unroll
        for (int it = 0; it < 8; ++it) {
            int idx = it * 256 + t;
            int cc = idx >> 4, n4 = (idx & 15) << 2;
            int ch = nt * 128 + cc;
            float bi = bp[ch];
            size_t off = (size_t)b * 65536 + (size_t)ch * 64 + n4;
            float4 xv = *(const float4*)(x + off);
            float4 v;
            v.x = g * (tile[(n4 + 0) * 130 + cc] + bi) + og * xv.x;
            v.y = g * (tile[(n4 + 1) * 130 + cc] + bi) + og * xv.y;
            v.z = g * (tile[(n4 + 2) * 130 + cc] + bi) + og * xv.z;
            v.w = g * (tile[(n4 + 3) * 130 + cc] + bi) + og * xv.w;
            ushort4 hv;
            hv.x = f16r(v.x); hv.y = f16r(v.y); hv.z = f16r(v.z); hv.w = f16r(v.w);
            *(ushort4*)(g_res16 + off) = hv;
            s1 += v.x + v.y + v.z + v.w;
            s2 += v.x * v.x + v.y * v.y + v.z * v.z + v.w * v.w;
        }
        // deterministic CTA reduction of partial stats
        #pragma unroll
        for (int o = 16; o; o >>= 1) {
            s1 += __shfl_xor_sync(0xffffffffu, s1, o);
            s2 += __shfl_xor_sync(0xffffffffu, s2, o);
        }
        if (lane == 0) { red1[wid] = s1; red2[wid] = s2; }
        __syncthreads();
        if (t == 0) {
            float a1 = 0.f, a2 = 0.f;
            #pragma unroll
            for (int w = 0; w < 8; ++w) { a1 += red1[w]; a2 += red2[w]; }
            g_partial[b * 8 + nt] = make_float2(a1, a2);
        }
        __syncthreads();
    }
}

// ---------------------------------------------------------------------------
// Attention (tensor-core): one CTA per (b,h), 128 threads / 4 warps.
// ---------------------------------------------------------------------------
__global__ void __launch_bounds__(128) attn_kernel(const float* __restrict__ temp_p)
{
    __shared__ __align__(128) u16 qs[4096];   // [n][d] fp16, sw128
    __shared__ __align__(128) u16 kk[4096];   // [m][d]
    __shared__ __align__(128) u16 vv[4096];   // [m][d]
    __shared__ float scq[64], sck[64];

    const int t = threadIdx.x, lane = t & 31, wid = t >> 5;
    const int b = blockIdx.x >> 4, h = blockIdx.x & 15;
    const u32 q0 = smem_u32(qs), k0 = smem_u32(kk), v0 = smem_u32(vv);

    // ---- load q/k/v tiles (64 x 64 fp16 each) via cp.async ----
    {
        u32 bases[3] = {q0, k0, v0};
        #pragma unroll
        for (int i = 0; i < 12; ++i) {
            int idx = t + i * 128;           // 0..1535
            int arr = idx >> 9, rem = idx & 511;
            int row = rem >> 3, ch = rem & 7;
            u32 dst = bases[arr] + row * 128 + ((ch ^ (row & 7)) << 4);
            const char* src = (const char*)(g_qkv16 + (size_t)arr * QKVSZ)
                            + ((size_t)(b * 64 + row) * 1024 + h * 64) * 2 + ch * 16;
            cpa16(dst, src);
        }
        CP_COMMIT();
        CP_WAIT0();
        __syncthreads();
    }

    // ---- per-d column sums of squares (vectorized: u32 loads, d-pairs) ----
    {
        float tinv = 1.0f / (temp_p[0] + 1e-6f);
        const u16* barr = (wid < 2) ? qs : kk;
        const int dp = ((wid & 1) << 4) + (lane & 15);   // 0..31
        const int half = lane >> 4;                       // 0: rows 0-31, 1: 32-63
        const int cb = dp >> 2;
        const int io = (dp * 4) & 15;
        float sx = 0.f, sy = 0.f;
        #pragma unroll 8
        for (int i = 0; i < 32; ++i) {
            int row = half * 32 + i;
            u32 off = (u32)(row * 128 + ((cb ^ (row & 7)) << 4) + io) >> 1;
            u32 v = *(const u32*)(barr + off);
            float2 f = __half22float2(*(__half2*)&v);
            sx += f.x * f.x;
            sy += f.y * f.y;
        }
        sx += __shfl_xor_sync(0xffffffffu, sx, 16);
        sy += __shfl_xor_sync(0xffffffffu, sy, 16);
        if (lane < 16) {
            float2 inv;
            inv.x = 1.0f / fmaxf(sqrtf(sx), 1e-12f);
            inv.y = 1.0f / fmaxf(sqrtf(sy), 1e-12f);
            if (wid < 2) *(float2*)&scq[dp * 2] = inv;
            else         *(float2*)&sck[dp * 2] = inv;
        }
        __syncthreads();
        if (t < 64) scq[t] = scq[t] * sck[t] * tinv;
        __syncthreads();
    }

    // ---- fold combined scale into q (fp16, in place) ----
    {
        u32* qw = (u32*)qs;
        #pragma unroll
        for (int i = 0; i < 16; ++i) {
            int idx = t + i * 128;
            int row = idx >> 5, pos = idx & 31;
            int ui = (row * 128 + (((pos >> 2) ^ (row & 7)) << 4) + (pos & 3) * 4) >> 2;
            float2 f = __half22float2(*(__half2*)&qw[ui]);
            f.x *= scq[pos * 2];
            f.y *= scq[pos * 2 + 1];
            qw[ui] = packh2(f.x, f.y);
        }
        __syncthreads();
    }

    // ---- S = qhat^T khat ----
    const int wm = wid << 4;
    float sa[8][4];
    #pragma unroll
    for (int j = 0; j < 8; ++j) { sa[j][0]=0.f; sa[j][1]=0.f; sa[j][2]=0.f; sa[j][3]=0.f; }
    {
        const int arow = lane & 15, akb = (lane >> 4) << 4;
        const int br = (lane & 7) + ((lane & 16) >> 1), bkb = (lane & 8) << 1;
        #pragma unroll
        for (int ks = 0; ks < 4; ++ks) {
            int kb = ks * 32;
            u32 A[4];
            ldsm_x4(A, sw128(q0, wm + arow, kb + akb));
            #pragma unroll
            for (int jp = 0; jp < 4; ++jp) {
                u32 r[4];
                ldsm_x4(r, sw128(k0, jp * 16 + br, kb + bkb));
                mma16816(sa[jp * 2], A, r);
                mma16816(sa[jp * 2 + 1], A, r + 2);
            }
        }
    }

    // ---- softmax + repack P into A-fragments ----
    u32 pa[4][4];
    {
        float mx0 = -1e30f, mx1 = -1e30f;
        #pragma unroll
        for (int j = 0; j < 8; ++j) {
            mx0 = fmaxf(mx0, fmaxf(sa[j][0], sa[j][1]));
            mx1 = fmaxf(mx1, fmaxf(sa[j][2], sa[j][3]));
        }
        #pragma unroll
        for (int o = 1; o <= 2; o <<= 1) {
            mx0 = fmaxf(mx0, __shfl_xor_sync(0xffffffffu, mx0, o));
            mx1 = fmaxf(mx1, __shfl_xor_sync(0xffffffffu, mx1, o));
        }
        float sum0 = 0.f, sum1 = 0.f;
        #pragma unroll
        for (int j = 0; j < 8; ++j) {
            sa[j][0] = __expf(sa[j][0] - mx0); sum0 += sa[j][0];
            sa[j][1] = __expf(sa[j][1] - mx0); sum0 += sa[j][1];
            sa[j][2] = __expf(sa[j][2] - mx1); sum1 += sa[j][2];
            sa[j][3] = __expf(sa[j][3] - mx1); sum1 += sa[j][3];
        }
        #pragma unroll
        for (int o = 1; o <= 2; o <<= 1) {
            sum0 += __shfl_xor_sync(0xffffffffu, sum0, o);
            sum1 += __shfl_xor_sync(0xffffffffu, sum1, o);
        }
        float r0 = 1.0f / sum0, r1 = 1.0f / sum1;
        #pragma unroll
        for (int ks = 0; ks < 4; ++ks) {
            pa[ks][0] = packh2(sa[2*ks][0] * r0, sa[2*ks][1] * r0);
            pa[ks][1] = packh2(sa[2*ks][2] * r1, sa[2*ks][3] * r1);
            pa[ks][2] = packh2(sa[2*ks+1][0] * r0, sa[2*ks+1][1] * r0);
            pa[ks][3] = packh2(sa[2*ks+1][2] * r1, sa[2*ks+1][3] * r1);
        }
    }

    // ---- O = P V ----
    float oa[8][4];
    #pragma unroll
    for (int j = 0; j < 8; ++j) { oa[j][0]=0.f; oa[j][1]=0.f; oa[j][2]=0.f; oa[j][3]=0.f; }
    {
        const int vrow = lane & 15, vdb = (lane >> 4) << 4;
        #pragma unroll
        for (int ks = 0; ks < 4; ++ks) {
            #pragma unroll
            for (int Dp = 0; Dp < 4; ++Dp) {
                u32 r[4];
                ldsm_x4t(r, sw128(v0, ks * 16 + vrow, Dp * 32 + vdb));
                mma16816(oa[Dp * 2], pa[ks], r);
                mma16816(oa[Dp * 2 + 1], pa[ks], r + 2);
            }
        }
    }
    __syncthreads();

    // ---- bounce O through smem, coalesced fp16 writes ----
    {
        u32* bn = (u32*)qs;
        int grp = lane >> 2, tg = lane & 3;
        #pragma unroll
        for (int jd = 0; jd < 8; ++jd) {
            int c = jd * 4 + tg;
            bn[(wm + grp) * 33 + c]     = packh2(oa[jd][0], oa[jd][1]);
            bn[(wm + grp + 8) * 33 + c] = packh2(oa[jd][2], oa[jd][3]);
        }
        __syncthreads();
        u16* outg = g_of16 + (size_t)(b * 64) * 1024 + h * 64;
        #pragma unroll
        for (int i = 0; i < 16; ++i) {
            int idx = t + i * 128;
            int row = idx >> 5, c = idx & 31;
            *(u32*)(outg + (size_t)row * 1024 + c * 2) = bn[row * 33 + c];
        }
    }
}

// ---------------------------------------------------------------------------
// LN apply: one CTA per batch, 512 threads. Stats from g_partial (8 per batch),
// single pass over fp16 residual.  y = (r - mu) * rstd * ln_w + ln_b
// ---------------------------------------------------------------------------
__global__ void __launch_bounds__(512) ln_kernel(
    const float* __restrict__ lnw, const float* __restrict__ lnb,
    float* __restrict__ y)
{
    __shared__ float sh[2];
    const int b = blockIdx.x, t = threadIdx.x;
    if (t == 0) {
        float s1 = 0.f, s2 = 0.f;
        #pragma unroll
        for (int w = 0; w < 8; ++w) {
            float2 p = g_partial[b * 8 + w];
            s1 += p.x; s2 += p.y;
        }
        float mu  = s1 * (1.0f / 65536.0f);
        float var = s2 * (1.0f / 65536.0f) - mu * mu;
        sh[0] = mu;
        sh[1] = rsqrtf(var + 1e-5f);
    }
    __syncthreads();
    const float mu = sh[0], rs = sh[1];
    const u16* rb = g_res16 + (size_t)b * 65536;
    float* yb = y + (size_t)b * 65536;
    #pragma unroll 2
    for (int i = t * 8; i < 65536; i += 4096) {
        uint4 pr = *(const uint4*)(rb + i);      // 8 fp16 residuals
        float2 p0 = __half22float2(*(__half2*)&pr.x);
        float2 p1 = __half22float2(*(__half2*)&pr.y);
        float2 p2 = __half22float2(*(__half2*)&pr.z);
        float2 p3 = __half22float2(*(__half2*)&pr.w);
        float4 w0 = *(const float4*)(lnw + i);
        float4 w1 = *(const float4*)(lnw + i + 4);
        float4 b0 = *(const float4*)(lnb + i);
        float4 b1 = *(const float4*)(lnb + i + 4);
        float4 o0, o1;
        o0.x = (p0.x - mu) * rs * w0.x + b0.x;
        o0.y = (p0.y - mu) * rs * w0.y + b0.y;
        o0.z = (p1.x - mu) * rs * w0.z + b0.z;
        o0.w = (p1.y - mu) * rs * w0.w + b0.w;
        o1.x = (p2.x - mu) * rs * w1.x + b1.x;
        o1.y = (p2.y - mu) * rs * w1.y + b1.y;
        o1.z = (p3.x - mu) * rs * w1.z + b1.z;
        o1.w = (p3.y - mu) * rs * w1.w + b1.w;
        *(float4*)(yb + i) = o0;
        *(float4*)(yb + i + 4) = o1;
    }
}

// ---------------------------------------------------------------------------
extern "C" void kernel_launch(void* const* d_in, const int* in_sizes, int n_in,
                              void* d_out, int out_size)
{
    const float* x     = (const float*)d_in[0];
    const float* Wq    = (const float*)d_in[1];
    const float* bq    = (const float*)d_in[2];
    const float* Wk    = (const float*)d_in[3];
    const float* bk    = (const float*)d_in[4];
    const float* Wv    = (const float*)d_in[5];
    const float* bv    = (const float*)d_in[6];
    const float* Wp    = (const float*)d_in[7];
    const float* bp    = (const float*)d_in[8];
    const float* gamma = (const float*)d_in[9];
    const float* temp  = (const float*)d_in[10];
    const float* lnw   = (const float*)d_in[11];
    const float* lnb   = (const float*)d_in[12];
    float* y = (float*)d_out;

    cudaFuncSetAttribute(qkv_gemm_kernel, cudaFuncAttributeMaxDynamicSharedMemorySize, SM_GEMM);
    cudaFuncSetAttribute(proj_gemm_kernel, cudaFuncAttributeMaxDynamicSharedMemorySize, SM_GEMM);

    prep_all_kernel<<<4096 + BB, 256>>>(Wq, Wk, Wv, Wp, x);
    qkv_gemm_kernel<<<dim3(24, 512), 256, SM_GEMM>>>(bq, bk, bv);
    attn_kernel<<<BB * NH, 128>>>(temp);
    proj_gemm_kernel<<<dim3(8, 512), 256, SM_GEMM>>>(bp, x, gamma);
    ln_kernel<<<BB, 512>>>(lnw, lnb, y);
}